// round 3
// baseline (speedup 1.0000x reference)
#include <cuda_runtime.h>
#include <cstdint>

// Problem constants (shapes fixed by dataset)
#define NN 50000
#define EE 800000

// ---------------- scratch (no allocation allowed) ----------------
__device__ __align__(16) float g_deg[NN];
__device__ __align__(16) float g_dinv[NN];
__device__ __align__(16) int   g_src[EE];
__device__ __align__(16) int   g_dst[EE];
__device__ __align__(16) float g_norm[EE];
__device__ __align__(16) float g_h1[(size_t)NN * 128];
__device__ __align__(16) float g_agg1[(size_t)NN * 128];  // reused as relu(layer1) output
__device__ __align__(16) float g_h2[(size_t)NN * 64];
__device__ __align__(16) float g_agg2[(size_t)NN * 64];
__device__ int g_is64;   // 1 if edge_index buffer is int64, 0 if int32

// ---------------- dtype detect: int64 arrays of small nonneg values have
// zero high words at every odd 32-bit position ----------------
__global__ void detect_dtype(const int* __restrict__ w, int* __restrict__ flag) {
    if (threadIdx.x == 0 && blockIdx.x == 0) {
        int is64 = 1;
        for (int i = 1; i < 64; i += 2)
            if (w[i] != 0) { is64 = 0; break; }
        *flag = is64;
    }
}

// ---------------- init: zero aggregators, deg = 1 (self loop) ----------------
__global__ void init_kernel(float* __restrict__ agg1, float* __restrict__ agg2,
                            float* __restrict__ deg, int n) {
    int i = blockIdx.x * blockDim.x + threadIdx.x;
    float4 z = make_float4(0.f, 0.f, 0.f, 0.f);
    if (i < n * 32) ((float4*)agg1)[i] = z;
    if (i < n * 16) ((float4*)agg2)[i] = z;
    if (i < n) deg[i] = 1.0f;
}

// ---------------- edge prep: decode indices, degree histogram ----------------
__global__ void prep_edges(const void* __restrict__ ei,
                           int* __restrict__ src, int* __restrict__ dst,
                           float* __restrict__ deg, const int* __restrict__ is64f,
                           int nE, int n) {
    int e = blockIdx.x * blockDim.x + threadIdx.x;
    if (e >= nE) return;
    int s, d;
    if (*is64f) {
        s = (int)((const long long*)ei)[e];
        d = (int)((const long long*)ei)[nE + e];
    } else {
        s = ((const int*)ei)[e];
        d = ((const int*)ei)[nE + e];
    }
    // clamp defensively: never let a bad index produce an OOB atomic
    s = min(max(s, 0), n - 1);
    d = min(max(d, 0), n - 1);
    src[e] = s;
    dst[e] = d;
    atomicAdd(&deg[d], 1.0f);
}

__global__ void compute_dinv(const float* __restrict__ deg, float* __restrict__ dinv, int n) {
    int i = blockIdx.x * blockDim.x + threadIdx.x;
    if (i < n) dinv[i] = rsqrtf(deg[i]);
}

__global__ void compute_norm(const int* __restrict__ src, const int* __restrict__ dst,
                             const float* __restrict__ dinv, float* __restrict__ nrm, int nE) {
    int e = blockIdx.x * blockDim.x + threadIdx.x;
    if (e >= nE) return;
    nrm[e] = dinv[src[e]] * dinv[dst[e]];
}

// ---------------- GEMM: H[n,128] = X[n,128] @ W[128,128] ----------------
// 256 threads = 8 warps; 64 rows/block (8 rows/warp). Lane j -> cols 4j..4j+3.
__global__ void gemm128(const float* __restrict__ X, const float* __restrict__ W,
                        float* __restrict__ H, int n) {
    __shared__ float xs[64][128];
    int warp = threadIdx.x >> 5;
    int lane = threadIdx.x & 31;
    int rowBase = blockIdx.x * 64;
    int nrows = n - rowBase; if (nrows > 64) nrows = 64;

    for (int i = threadIdx.x; i < nrows * 32; i += 256) {
        int r = i >> 5, c = i & 31;
        ((float4*)&xs[r][0])[c] = ((const float4*)(X + (size_t)(rowBase + r) * 128))[c];
    }
    __syncthreads();

    float4 acc[8];
#pragma unroll
    for (int r = 0; r < 8; r++) acc[r] = make_float4(0.f, 0.f, 0.f, 0.f);

    int r0 = warp * 8;
#pragma unroll 8
    for (int k = 0; k < 128; k++) {
        float4 wv = __ldg((const float4*)(W + (size_t)k * 128) + lane);
#pragma unroll
        for (int r = 0; r < 8; r++) {
            float xv = xs[r0 + r][k];
            acc[r].x += xv * wv.x;
            acc[r].y += xv * wv.y;
            acc[r].z += xv * wv.z;
            acc[r].w += xv * wv.w;
        }
    }

#pragma unroll
    for (int r = 0; r < 8; r++) {
        int row = rowBase + r0 + r;
        if (row < n) ((float4*)(H + (size_t)row * 128))[lane] = acc[r];
    }
}

// ---------------- GEMM: H[n,64] = X[n,128] @ W[128,64] ----------------
__global__ void gemm64(const float* __restrict__ X, const float* __restrict__ W,
                       float* __restrict__ H, int n) {
    __shared__ float xs[64][128];
    int warp = threadIdx.x >> 5;
    int lane = threadIdx.x & 31;
    int rowBase = blockIdx.x * 64;
    int nrows = n - rowBase; if (nrows > 64) nrows = 64;

    for (int i = threadIdx.x; i < nrows * 32; i += 256) {
        int r = i >> 5, c = i & 31;
        ((float4*)&xs[r][0])[c] = ((const float4*)(X + (size_t)(rowBase + r) * 128))[c];
    }
    __syncthreads();

    float2 acc[8];
#pragma unroll
    for (int r = 0; r < 8; r++) acc[r] = make_float2(0.f, 0.f);

    int r0 = warp * 8;
#pragma unroll 8
    for (int k = 0; k < 128; k++) {
        float2 wv = __ldg((const float2*)(W + (size_t)k * 64) + lane);
#pragma unroll
        for (int r = 0; r < 8; r++) {
            float xv = xs[r0 + r][k];
            acc[r].x += xv * wv.x;
            acc[r].y += xv * wv.y;
        }
    }

#pragma unroll
    for (int r = 0; r < 8; r++) {
        int row = rowBase + r0 + r;
        if (row < n) ((float2*)(H + (size_t)row * 64))[lane] = acc[r];
    }
}

// ---------------- scatter: agg[dst] += h[src] * norm ----------------
__global__ void scatter128(const float* __restrict__ H, float* __restrict__ AGG,
                           const int* __restrict__ src, const int* __restrict__ dst,
                           const float* __restrict__ nrm, int nE) {
    int i = blockIdx.x * blockDim.x + threadIdx.x;
    int e = i >> 5;
    if (e >= nE) return;
    int c = i & 31;
    int s = src[e], d = dst[e];
    float w = nrm[e];
    float4 v = ((const float4*)(H + (size_t)s * 128))[c];
    float* a = AGG + (size_t)d * 128 + c * 4;
    atomicAdd(a + 0, v.x * w);
    atomicAdd(a + 1, v.y * w);
    atomicAdd(a + 2, v.z * w);
    atomicAdd(a + 3, v.w * w);
}

__global__ void scatter64(const float* __restrict__ H, float* __restrict__ AGG,
                          const int* __restrict__ src, const int* __restrict__ dst,
                          const float* __restrict__ nrm, int nE) {
    int i = blockIdx.x * blockDim.x + threadIdx.x;
    int e = i >> 4;
    if (e >= nE) return;
    int c = i & 15;
    int s = src[e], d = dst[e];
    float w = nrm[e];
    float4 v = ((const float4*)(H + (size_t)s * 64))[c];
    float* a = AGG + (size_t)d * 64 + c * 4;
    atomicAdd(a + 0, v.x * w);
    atomicAdd(a + 1, v.y * w);
    atomicAdd(a + 2, v.z * w);
    atomicAdd(a + 3, v.w * w);
}

// ---------------- finalize layer 1: relu(agg + h/deg + b), in place ----------------
__global__ void finalize_relu128(float* __restrict__ agg, const float* __restrict__ H,
                                 const float* __restrict__ deg, const float* __restrict__ bias,
                                 int n) {
    int i = blockIdx.x * blockDim.x + threadIdx.x;
    if (i >= n * 32) return;
    int row = i >> 5;
    int c = i & 31;
    float id = 1.0f / deg[row];
    float4 a = ((float4*)agg)[i];
    float4 h = ((const float4*)H)[i];
    float4 b = ((const float4*)bias)[c];
    a.x = fmaxf(a.x + h.x * id + b.x, 0.f);
    a.y = fmaxf(a.y + h.y * id + b.y, 0.f);
    a.z = fmaxf(a.z + h.z * id + b.z, 0.f);
    a.w = fmaxf(a.w + h.w * id + b.w, 0.f);
    ((float4*)agg)[i] = a;
}

// ---------------- finalize layer 2: out = agg + h/deg + b ----------------
__global__ void finalize_out64(const float* __restrict__ agg, const float* __restrict__ H,
                               const float* __restrict__ deg, const float* __restrict__ bias,
                               float* __restrict__ out, int n) {
    int i = blockIdx.x * blockDim.x + threadIdx.x;
    if (i >= n * 16) return;
    int row = i >> 4;
    int c = i & 15;
    float id = 1.0f / deg[row];
    float4 a = ((const float4*)agg)[i];
    float4 h = ((const float4*)H)[i];
    float4 b = ((const float4*)bias)[c];
    a.x = a.x + h.x * id + b.x;
    a.y = a.y + h.y * id + b.y;
    a.z = a.z + h.z * id + b.z;
    a.w = a.w + h.w * id + b.w;
    ((float4*)out)[i] = a;
}

// ---------------- launch ----------------
extern "C" void kernel_launch(void* const* d_in, const int* in_sizes, int n_in,
                              void* d_out, int out_size) {
    const float* x  = (const float*)d_in[0];
    const void*  ei = d_in[1];
    const float* W1 = (const float*)d_in[2];
    const float* b1 = (const float*)d_in[3];
    const float* W2 = (const float*)d_in[4];
    const float* b2 = (const float*)d_in[5];
    float* out = (float*)d_out;

    int n  = in_sizes[0] / 128;   // 50000
    int nE = in_sizes[1] / 2;     // 800000 (element count is 2*E regardless of dtype)

    float *p_deg, *p_dinv, *p_norm, *p_h1, *p_agg1, *p_h2, *p_agg2;
    int *p_src, *p_dst, *p_is64;
    cudaGetSymbolAddress((void**)&p_deg,  g_deg);
    cudaGetSymbolAddress((void**)&p_dinv, g_dinv);
    cudaGetSymbolAddress((void**)&p_norm, g_norm);
    cudaGetSymbolAddress((void**)&p_h1,   g_h1);
    cudaGetSymbolAddress((void**)&p_agg1, g_agg1);
    cudaGetSymbolAddress((void**)&p_h2,   g_h2);
    cudaGetSymbolAddress((void**)&p_agg2, g_agg2);
    cudaGetSymbolAddress((void**)&p_src,  g_src);
    cudaGetSymbolAddress((void**)&p_dst,  g_dst);
    cudaGetSymbolAddress((void**)&p_is64, g_is64);

    const int T = 256;
    detect_dtype<<<1, 32>>>((const int*)ei, p_is64);
    init_kernel<<<(n * 32 + T - 1) / T, T>>>(p_agg1, p_agg2, p_deg, n);
    prep_edges<<<(nE + T - 1) / T, T>>>(ei, p_src, p_dst, p_deg, p_is64, nE, n);
    compute_dinv<<<(n + T - 1) / T, T>>>(p_deg, p_dinv, n);
    compute_norm<<<(nE + T - 1) / T, T>>>(p_src, p_dst, p_dinv, p_norm, nE);

    // layer 1
    gemm128<<<(n + 63) / 64, T>>>(x, W1, p_h1, n);
    scatter128<<<((size_t)nE * 32 + T - 1) / T, T>>>(p_h1, p_agg1, p_src, p_dst, p_norm, nE);
    finalize_relu128<<<(n * 32 + T - 1) / T, T>>>(p_agg1, p_h1, p_deg, b1, n);

    // layer 2 (input = p_agg1, in place)
    gemm64<<<(n + 63) / 64, T>>>(p_agg1, W2, p_h2, n);
    scatter64<<<((size_t)nE * 16 + T - 1) / T, T>>>(p_h2, p_agg2, p_src, p_dst, p_norm, nE);
    finalize_out64<<<(n * 16 + T - 1) / T, T>>>(p_agg2, p_h2, p_deg, b2, out, n);
}

// round 4
// speedup vs baseline: 2.1670x; 2.1670x over previous
#include <cuda_runtime.h>
#include <cstdint>

#define NN 50000
#define EE 800000

// ---------------- scratch ----------------
__device__ __align__(16) int   g_hist[NN];
__device__ __align__(16) int   g_rowptr[NN + 1];
__device__ __align__(16) int   g_fill[NN];
__device__ __align__(16) float g_dinv[NN];
__device__ __align__(16) int   g_src[EE];
__device__ __align__(16) int   g_dst[EE];
__device__ __align__(16) int   g_csr_src[EE];
__device__ __align__(16) float g_csr_norm[EE];
__device__ __align__(16) float g_h1[(size_t)NN * 128];
__device__ __align__(16) float g_x2[(size_t)NN * 128];   // relu(layer1)
__device__ __align__(16) float g_h2[(size_t)NN * 64];
__device__ int g_is64;

// ---------------- dtype detect ----------------
__global__ void detect_dtype(const int* __restrict__ w, int* __restrict__ flag) {
    if (threadIdx.x == 0 && blockIdx.x == 0) {
        int is64 = 1;
        for (int i = 1; i < 64; i += 2)
            if (w[i] != 0) { is64 = 0; break; }
        *flag = is64;
    }
}

// ---------------- zero histogram ----------------
__global__ void zero_hist(int* __restrict__ hist, int n) {
    int i = blockIdx.x * blockDim.x + threadIdx.x;
    if (i < n) hist[i] = 0;
}

// ---------------- edge decode + degree histogram ----------------
__global__ void prep_edges(const void* __restrict__ ei,
                           int* __restrict__ src, int* __restrict__ dst,
                           int* __restrict__ hist, const int* __restrict__ is64f,
                           int nE, int n) {
    int e = blockIdx.x * blockDim.x + threadIdx.x;
    if (e >= nE) return;
    int s, d;
    if (*is64f) {
        s = (int)((const long long*)ei)[e];
        d = (int)((const long long*)ei)[nE + e];
    } else {
        s = ((const int*)ei)[e];
        d = ((const int*)ei)[nE + e];
    }
    s = min(max(s, 0), n - 1);
    d = min(max(d, 0), n - 1);
    src[e] = s;
    dst[e] = d;
    atomicAdd(&hist[d], 1);
}

// ---------------- single-block exclusive scan + dinv ----------------
__global__ void scan_kernel(const int* __restrict__ hist, int* __restrict__ rowptr,
                            int* __restrict__ fill, float* __restrict__ dinv, int n) {
    __shared__ int warpsum[32];
    __shared__ int carry_s;
    int t = threadIdx.x, lane = t & 31, wid = t >> 5;
    if (t == 0) carry_s = 0;
    __syncthreads();
    for (int base = 0; base < n; base += 1024) {
        int idx = base + t;
        int v = (idx < n) ? hist[idx] : 0;
        if (idx < n) dinv[idx] = rsqrtf(1.0f + (float)v);
        int x = v;
#pragma unroll
        for (int off = 1; off < 32; off <<= 1) {
            int y = __shfl_up_sync(0xffffffff, x, off);
            if (lane >= off) x += y;
        }
        if (lane == 31) warpsum[wid] = x;
        __syncthreads();
        if (wid == 0) {
            int s = warpsum[lane];
#pragma unroll
            for (int off = 1; off < 32; off <<= 1) {
                int y = __shfl_up_sync(0xffffffff, s, off);
                if (lane >= off) s += y;
            }
            warpsum[lane] = s;
        }
        __syncthreads();
        int warpoff = (wid > 0) ? warpsum[wid - 1] : 0;
        int incl = x + warpoff;
        int excl = incl - v;
        int carry = carry_s;
        if (idx < n) { int p = carry + excl; rowptr[idx] = p; fill[idx] = p; }
        __syncthreads();
        if (t == 1023) carry_s = carry + incl;
        __syncthreads();
    }
    if (threadIdx.x == 0) rowptr[n] = carry_s;
}

// ---------------- CSR fill: bucket edges by dst ----------------
__global__ void fill_csr(const int* __restrict__ src, const int* __restrict__ dst,
                         const float* __restrict__ dinv, int* __restrict__ fill,
                         int* __restrict__ csr_src, float* __restrict__ csr_norm, int nE) {
    int e = blockIdx.x * blockDim.x + threadIdx.x;
    if (e >= nE) return;
    int s = src[e], d = dst[e];
    int pos = atomicAdd(&fill[d], 1);
    csr_src[pos] = s;
    csr_norm[pos] = dinv[s] * dinv[d];
}

// ---------------- GEMM: H[n,128] = X[n,128] @ W[128,128] ----------------
__global__ void gemm128(const float* __restrict__ X, const float* __restrict__ W,
                        float* __restrict__ H, int n) {
    __shared__ float xs[64][128];
    int warp = threadIdx.x >> 5;
    int lane = threadIdx.x & 31;
    int rowBase = blockIdx.x * 64;
    int nrows = n - rowBase; if (nrows > 64) nrows = 64;

    for (int i = threadIdx.x; i < nrows * 32; i += 256) {
        int r = i >> 5, c = i & 31;
        ((float4*)&xs[r][0])[c] = ((const float4*)(X + (size_t)(rowBase + r) * 128))[c];
    }
    __syncthreads();

    float4 acc[8];
#pragma unroll
    for (int r = 0; r < 8; r++) acc[r] = make_float4(0.f, 0.f, 0.f, 0.f);

    int r0 = warp * 8;
#pragma unroll 8
    for (int k = 0; k < 128; k++) {
        float4 wv = __ldg((const float4*)(W + (size_t)k * 128) + lane);
#pragma unroll
        for (int r = 0; r < 8; r++) {
            float xv = xs[r0 + r][k];
            acc[r].x += xv * wv.x;
            acc[r].y += xv * wv.y;
            acc[r].z += xv * wv.z;
            acc[r].w += xv * wv.w;
        }
    }

#pragma unroll
    for (int r = 0; r < 8; r++) {
        int row = rowBase + r0 + r;
        if (row < n) ((float4*)(H + (size_t)row * 128))[lane] = acc[r];
    }
}

// ---------------- GEMM: H[n,64] = X[n,128] @ W[128,64] ----------------
__global__ void gemm64(const float* __restrict__ X, const float* __restrict__ W,
                       float* __restrict__ H, int n) {
    __shared__ float xs[64][128];
    int warp = threadIdx.x >> 5;
    int lane = threadIdx.x & 31;
    int rowBase = blockIdx.x * 64;
    int nrows = n - rowBase; if (nrows > 64) nrows = 64;

    for (int i = threadIdx.x; i < nrows * 32; i += 256) {
        int r = i >> 5, c = i & 31;
        ((float4*)&xs[r][0])[c] = ((const float4*)(X + (size_t)(rowBase + r) * 128))[c];
    }
    __syncthreads();

    float2 acc[8];
#pragma unroll
    for (int r = 0; r < 8; r++) acc[r] = make_float2(0.f, 0.f);

    int r0 = warp * 8;
#pragma unroll 8
    for (int k = 0; k < 128; k++) {
        float2 wv = __ldg((const float2*)(W + (size_t)k * 64) + lane);
#pragma unroll
        for (int r = 0; r < 8; r++) {
            float xv = xs[r0 + r][k];
            acc[r].x += xv * wv.x;
            acc[r].y += xv * wv.y;
        }
    }

#pragma unroll
    for (int r = 0; r < 8; r++) {
        int row = rowBase + r0 + r;
        if (row < n) ((float2*)(H + (size_t)row * 64))[lane] = acc[r];
    }
}

// ---------------- aggregate layer 1: warp per node, fused self+bias+relu ----------------
__global__ void aggregate128(const float* __restrict__ H, const int* __restrict__ rowptr,
                             const int* __restrict__ csr_src, const float* __restrict__ csr_norm,
                             const float* __restrict__ dinv, const float* __restrict__ bias,
                             float* __restrict__ out, int n) {
    int node = blockIdx.x * (blockDim.x >> 5) + (threadIdx.x >> 5);
    if (node >= n) return;
    int lane = threadIdx.x & 31;
    int beg = rowptr[node], end = rowptr[node + 1];
    float di = dinv[node];
    float selfw = di * di;  // 1/deg

    const float4* H4 = (const float4*)H;
    float4 acc = H4[(size_t)node * 32 + lane];
    acc.x *= selfw; acc.y *= selfw; acc.z *= selfw; acc.w *= selfw;

    for (int e = beg; e < end; e++) {
        int s = __ldg(csr_src + e);
        float w = __ldg(csr_norm + e);
        float4 v = H4[(size_t)s * 32 + lane];
        acc.x += v.x * w; acc.y += v.y * w; acc.z += v.z * w; acc.w += v.w * w;
    }
    float4 b = ((const float4*)bias)[lane];
    acc.x = fmaxf(acc.x + b.x, 0.f);
    acc.y = fmaxf(acc.y + b.y, 0.f);
    acc.z = fmaxf(acc.z + b.z, 0.f);
    acc.w = fmaxf(acc.w + b.w, 0.f);
    ((float4*)out)[(size_t)node * 32 + lane] = acc;
}

// ---------------- aggregate layer 2: warp per node, float2 lanes, fused ----------------
__global__ void aggregate64(const float* __restrict__ H, const int* __restrict__ rowptr,
                            const int* __restrict__ csr_src, const float* __restrict__ csr_norm,
                            const float* __restrict__ dinv, const float* __restrict__ bias,
                            float* __restrict__ out, int n) {
    int node = blockIdx.x * (blockDim.x >> 5) + (threadIdx.x >> 5);
    if (node >= n) return;
    int lane = threadIdx.x & 31;
    int beg = rowptr[node], end = rowptr[node + 1];
    float di = dinv[node];
    float selfw = di * di;

    const float2* H2 = (const float2*)H;
    float2 acc = H2[(size_t)node * 32 + lane];
    acc.x *= selfw; acc.y *= selfw;

    for (int e = beg; e < end; e++) {
        int s = __ldg(csr_src + e);
        float w = __ldg(csr_norm + e);
        float2 v = H2[(size_t)s * 32 + lane];
        acc.x += v.x * w; acc.y += v.y * w;
    }
    float2 b = ((const float2*)bias)[lane];
    acc.x += b.x;
    acc.y += b.y;
    ((float2*)out)[(size_t)node * 32 + lane] = acc;
}

// ---------------- launch ----------------
extern "C" void kernel_launch(void* const* d_in, const int* in_sizes, int n_in,
                              void* d_out, int out_size) {
    const float* x  = (const float*)d_in[0];
    const void*  ei = d_in[1];
    const float* W1 = (const float*)d_in[2];
    const float* b1 = (const float*)d_in[3];
    const float* W2 = (const float*)d_in[4];
    const float* b2 = (const float*)d_in[5];
    float* out = (float*)d_out;

    int n  = in_sizes[0] / 128;   // 50000
    int nE = in_sizes[1] / 2;     // 800000

    int *p_hist, *p_rowptr, *p_fill, *p_src, *p_dst, *p_csr_src, *p_is64;
    float *p_dinv, *p_csr_norm, *p_h1, *p_x2, *p_h2;
    cudaGetSymbolAddress((void**)&p_hist,     g_hist);
    cudaGetSymbolAddress((void**)&p_rowptr,   g_rowptr);
    cudaGetSymbolAddress((void**)&p_fill,     g_fill);
    cudaGetSymbolAddress((void**)&p_dinv,     g_dinv);
    cudaGetSymbolAddress((void**)&p_src,      g_src);
    cudaGetSymbolAddress((void**)&p_dst,      g_dst);
    cudaGetSymbolAddress((void**)&p_csr_src,  g_csr_src);
    cudaGetSymbolAddress((void**)&p_csr_norm, g_csr_norm);
    cudaGetSymbolAddress((void**)&p_h1,       g_h1);
    cudaGetSymbolAddress((void**)&p_x2,       g_x2);
    cudaGetSymbolAddress((void**)&p_h2,       g_h2);
    cudaGetSymbolAddress((void**)&p_is64,     g_is64);

    const int T = 256;
    detect_dtype<<<1, 32>>>((const int*)ei, p_is64);
    zero_hist<<<(n + T - 1) / T, T>>>(p_hist, n);
    prep_edges<<<(nE + T - 1) / T, T>>>(ei, p_src, p_dst, p_hist, p_is64, nE, n);
    scan_kernel<<<1, 1024>>>(p_hist, p_rowptr, p_fill, p_dinv, n);
    fill_csr<<<(nE + T - 1) / T, T>>>(p_src, p_dst, p_dinv, p_fill, p_csr_src, p_csr_norm, nE);

    // layer 1: gemm + fused aggregate/self/bias/relu
    gemm128<<<(n + 63) / 64, T>>>(x, W1, p_h1, n);
    aggregate128<<<(n + 7) / 8, T>>>(p_h1, p_rowptr, p_csr_src, p_csr_norm, p_dinv, b1, p_x2, n);

    // layer 2
    gemm64<<<(n + 63) / 64, T>>>(p_x2, W2, p_h2, n);
    aggregate64<<<(n + 7) / 8, T>>>(p_h2, p_rowptr, p_csr_src, p_csr_norm, p_dinv, b2, out, n);
}

// round 5
// speedup vs baseline: 2.5360x; 1.1703x over previous
#include <cuda_runtime.h>
#include <cstdint>

#define NN 50000
#define EE 800000
#define SCAN_B 1024
#define NBLK ((NN + SCAN_B - 1) / SCAN_B)   // 49

// ---------------- scratch ----------------
__device__ __align__(16) int   g_hist[NN];
__device__ __align__(16) int   g_rowptr[NN + 1];
__device__ __align__(16) int   g_fill[NN];
__device__ __align__(16) int   g_blocksum[NBLK];
__device__ __align__(16) int   g_blockoff[NBLK];
__device__ __align__(16) float g_dinv[NN];
__device__ __align__(16) int   g_src[EE];
__device__ __align__(16) int   g_dst[EE];
__device__ __align__(16) int   g_csr_src[EE];
__device__ __align__(16) float g_csr_norm[EE];
__device__ __align__(16) float g_h1[(size_t)NN * 128];
__device__ __align__(16) float g_x2[(size_t)NN * 128];   // relu(layer1)
__device__ __align__(16) float g_h2[(size_t)NN * 64];
__device__ int g_is64;

// ---------------- dtype detect ----------------
__global__ void detect_dtype(const int* __restrict__ w, int* __restrict__ flag) {
    if (threadIdx.x == 0 && blockIdx.x == 0) {
        int is64 = 1;
        for (int i = 1; i < 64; i += 2)
            if (w[i] != 0) { is64 = 0; break; }
        *flag = is64;
    }
}

// ---------------- edge decode + degree histogram ----------------
__global__ void prep_edges(const void* __restrict__ ei,
                           int* __restrict__ src, int* __restrict__ dst,
                           int* __restrict__ hist, const int* __restrict__ is64f,
                           int nE, int n) {
    int e = blockIdx.x * blockDim.x + threadIdx.x;
    if (e >= nE) return;
    int s, d;
    if (*is64f) {
        s = (int)((const long long*)ei)[e];
        d = (int)((const long long*)ei)[nE + e];
    } else {
        s = ((const int*)ei)[e];
        d = ((const int*)ei)[nE + e];
    }
    s = min(max(s, 0), n - 1);
    d = min(max(d, 0), n - 1);
    src[e] = s;
    dst[e] = d;
    atomicAdd(&hist[d], 1);
}

// ---------------- phase 1: per-block exclusive scan (+dinv) ----------------
__global__ void block_scan(const int* __restrict__ hist, int* __restrict__ rowptr,
                           int* __restrict__ blocksum, float* __restrict__ dinv, int n) {
    __shared__ int warpsum[32];
    int t = threadIdx.x, lane = t & 31, wid = t >> 5;
    int idx = blockIdx.x * SCAN_B + t;
    int v = (idx < n) ? hist[idx] : 0;
    if (idx < n) dinv[idx] = rsqrtf(1.0f + (float)v);
    int x = v;
#pragma unroll
    for (int off = 1; off < 32; off <<= 1) {
        int y = __shfl_up_sync(0xffffffff, x, off);
        if (lane >= off) x += y;
    }
    if (lane == 31) warpsum[wid] = x;
    __syncthreads();
    if (wid == 0) {
        int s = warpsum[lane];
#pragma unroll
        for (int off = 1; off < 32; off <<= 1) {
            int y = __shfl_up_sync(0xffffffff, s, off);
            if (lane >= off) s += y;
        }
        warpsum[lane] = s;
    }
    __syncthreads();
    int warpoff = (wid > 0) ? warpsum[wid - 1] : 0;
    int excl = x + warpoff - v;
    if (idx < n) rowptr[idx] = excl;
    if (t == SCAN_B - 1) blocksum[blockIdx.x] = x + warpoff;
}

// ---------------- phase 2: scan block sums (NBLK <= 1024) ----------------
__global__ void scan_sums(const int* __restrict__ blocksum, int* __restrict__ blockoff,
                          int* __restrict__ rowptr, int n, int nblk) {
    __shared__ int warpsum[32];
    int t = threadIdx.x, lane = t & 31, wid = t >> 5;
    int v = (t < nblk) ? blocksum[t] : 0;
    int x = v;
#pragma unroll
    for (int off = 1; off < 32; off <<= 1) {
        int y = __shfl_up_sync(0xffffffff, x, off);
        if (lane >= off) x += y;
    }
    if (lane == 31) warpsum[wid] = x;
    __syncthreads();
    if (wid == 0) {
        int s = warpsum[lane];
#pragma unroll
        for (int off = 1; off < 32; off <<= 1) {
            int y = __shfl_up_sync(0xffffffff, s, off);
            if (lane >= off) s += y;
        }
        warpsum[lane] = s;
    }
    __syncthreads();
    int warpoff = (wid > 0) ? warpsum[wid - 1] : 0;
    if (t < nblk) blockoff[t] = x + warpoff - v;
    if (t == nblk - 1) rowptr[n] = x + warpoff;   // total edge count
}

// ---------------- phase 3: add offsets, copy to fill ----------------
__global__ void add_offsets(int* __restrict__ rowptr, int* __restrict__ fill,
                            const int* __restrict__ blockoff, int n) {
    int idx = blockIdx.x * SCAN_B + threadIdx.x;
    if (idx >= n) return;
    int p = rowptr[idx] + blockoff[blockIdx.x];
    rowptr[idx] = p;
    fill[idx] = p;
}

// ---------------- CSR fill: bucket edges by dst ----------------
__global__ void fill_csr(const int* __restrict__ src, const int* __restrict__ dst,
                         const float* __restrict__ dinv, int* __restrict__ fill,
                         int* __restrict__ csr_src, float* __restrict__ csr_norm, int nE) {
    int e = blockIdx.x * blockDim.x + threadIdx.x;
    if (e >= nE) return;
    int s = src[e], d = dst[e];
    int pos = atomicAdd(&fill[d], 1);
    csr_src[pos] = s;
    csr_norm[pos] = dinv[s] * dinv[d];
}

// ---------------- GEMM: H[n,128] = X[n,128] @ W[128,128] ----------------
__global__ void gemm128(const float* __restrict__ X, const float* __restrict__ W,
                        float* __restrict__ H, int n) {
    __shared__ float xs[64][128];
    int warp = threadIdx.x >> 5;
    int lane = threadIdx.x & 31;
    int rowBase = blockIdx.x * 64;
    int nrows = n - rowBase; if (nrows > 64) nrows = 64;

    for (int i = threadIdx.x; i < nrows * 32; i += 256) {
        int r = i >> 5, c = i & 31;
        ((float4*)&xs[r][0])[c] = ((const float4*)(X + (size_t)(rowBase + r) * 128))[c];
    }
    __syncthreads();

    float4 acc[8];
#pragma unroll
    for (int r = 0; r < 8; r++) acc[r] = make_float4(0.f, 0.f, 0.f, 0.f);

    int r0 = warp * 8;
#pragma unroll 8
    for (int k = 0; k < 128; k++) {
        float4 wv = __ldg((const float4*)(W + (size_t)k * 128) + lane);
#pragma unroll
        for (int r = 0; r < 8; r++) {
            float xv = xs[r0 + r][k];
            acc[r].x += xv * wv.x;
            acc[r].y += xv * wv.y;
            acc[r].z += xv * wv.z;
            acc[r].w += xv * wv.w;
        }
    }

#pragma unroll
    for (int r = 0; r < 8; r++) {
        int row = rowBase + r0 + r;
        if (row < n) ((float4*)(H + (size_t)row * 128))[lane] = acc[r];
    }
}

// ---------------- GEMM: H[n,64] = X[n,128] @ W[128,64] ----------------
__global__ void gemm64(const float* __restrict__ X, const float* __restrict__ W,
                       float* __restrict__ H, int n) {
    __shared__ float xs[64][128];
    int warp = threadIdx.x >> 5;
    int lane = threadIdx.x & 31;
    int rowBase = blockIdx.x * 64;
    int nrows = n - rowBase; if (nrows > 64) nrows = 64;

    for (int i = threadIdx.x; i < nrows * 32; i += 256) {
        int r = i >> 5, c = i & 31;
        ((float4*)&xs[r][0])[c] = ((const float4*)(X + (size_t)(rowBase + r) * 128))[c];
    }
    __syncthreads();

    float2 acc[8];
#pragma unroll
    for (int r = 0; r < 8; r++) acc[r] = make_float2(0.f, 0.f);

    int r0 = warp * 8;
#pragma unroll 8
    for (int k = 0; k < 128; k++) {
        float2 wv = __ldg((const float2*)(W + (size_t)k * 64) + lane);
#pragma unroll
        for (int r = 0; r < 8; r++) {
            float xv = xs[r0 + r][k];
            acc[r].x += xv * wv.x;
            acc[r].y += xv * wv.y;
        }
    }

#pragma unroll
    for (int r = 0; r < 8; r++) {
        int row = rowBase + r0 + r;
        if (row < n) ((float2*)(H + (size_t)row * 64))[lane] = acc[r];
    }
}

// ---------------- aggregate layer 1: warp per node, fused self+bias+relu ----------------
__global__ void aggregate128(const float* __restrict__ H, const int* __restrict__ rowptr,
                             const int* __restrict__ csr_src, const float* __restrict__ csr_norm,
                             const float* __restrict__ dinv, const float* __restrict__ bias,
                             float* __restrict__ out, int n) {
    int node = blockIdx.x * (blockDim.x >> 5) + (threadIdx.x >> 5);
    if (node >= n) return;
    int lane = threadIdx.x & 31;
    int beg = rowptr[node], end = rowptr[node + 1];
    float di = dinv[node];
    float selfw = di * di;  // 1/deg

    const float4* H4 = (const float4*)H;
    float4 acc = H4[(size_t)node * 32 + lane];
    acc.x *= selfw; acc.y *= selfw; acc.z *= selfw; acc.w *= selfw;

    for (int e = beg; e < end; e++) {
        int s = __ldg(csr_src + e);
        float w = __ldg(csr_norm + e);
        float4 v = H4[(size_t)s * 32 + lane];
        acc.x += v.x * w; acc.y += v.y * w; acc.z += v.z * w; acc.w += v.w * w;
    }
    float4 b = ((const float4*)bias)[lane];
    acc.x = fmaxf(acc.x + b.x, 0.f);
    acc.y = fmaxf(acc.y + b.y, 0.f);
    acc.z = fmaxf(acc.z + b.z, 0.f);
    acc.w = fmaxf(acc.w + b.w, 0.f);
    ((float4*)out)[(size_t)node * 32 + lane] = acc;
}

// ---------------- aggregate layer 2: warp per node, float2 lanes, fused ----------------
__global__ void aggregate64(const float* __restrict__ H, const int* __restrict__ rowptr,
                            const int* __restrict__ csr_src, const float* __restrict__ csr_norm,
                            const float* __restrict__ dinv, const float* __restrict__ bias,
                            float* __restrict__ out, int n) {
    int node = blockIdx.x * (blockDim.x >> 5) + (threadIdx.x >> 5);
    if (node >= n) return;
    int lane = threadIdx.x & 31;
    int beg = rowptr[node], end = rowptr[node + 1];
    float di = dinv[node];
    float selfw = di * di;

    const float2* H2 = (const float2*)H;
    float2 acc = H2[(size_t)node * 32 + lane];
    acc.x *= selfw; acc.y *= selfw;

    for (int e = beg; e < end; e++) {
        int s = __ldg(csr_src + e);
        float w = __ldg(csr_norm + e);
        float2 v = H2[(size_t)s * 32 + lane];
        acc.x += v.x * w; acc.y += v.y * w;
    }
    float2 b = ((const float2*)bias)[lane];
    acc.x += b.x;
    acc.y += b.y;
    ((float2*)out)[(size_t)node * 32 + lane] = acc;
}

// ---------------- launch ----------------
extern "C" void kernel_launch(void* const* d_in, const int* in_sizes, int n_in,
                              void* d_out, int out_size) {
    const float* x  = (const float*)d_in[0];
    const void*  ei = d_in[1];
    const float* W1 = (const float*)d_in[2];
    const float* b1 = (const float*)d_in[3];
    const float* W2 = (const float*)d_in[4];
    const float* b2 = (const float*)d_in[5];
    float* out = (float*)d_out;

    int n  = in_sizes[0] / 128;   // 50000
    int nE = in_sizes[1] / 2;     // 800000

    int *p_hist, *p_rowptr, *p_fill, *p_bsum, *p_boff, *p_src, *p_dst, *p_csr_src, *p_is64;
    float *p_dinv, *p_csr_norm, *p_h1, *p_x2, *p_h2;
    cudaGetSymbolAddress((void**)&p_hist,     g_hist);
    cudaGetSymbolAddress((void**)&p_rowptr,   g_rowptr);
    cudaGetSymbolAddress((void**)&p_fill,     g_fill);
    cudaGetSymbolAddress((void**)&p_bsum,     g_blocksum);
    cudaGetSymbolAddress((void**)&p_boff,     g_blockoff);
    cudaGetSymbolAddress((void**)&p_dinv,     g_dinv);
    cudaGetSymbolAddress((void**)&p_src,      g_src);
    cudaGetSymbolAddress((void**)&p_dst,      g_dst);
    cudaGetSymbolAddress((void**)&p_csr_src,  g_csr_src);
    cudaGetSymbolAddress((void**)&p_csr_norm, g_csr_norm);
    cudaGetSymbolAddress((void**)&p_h1,       g_h1);
    cudaGetSymbolAddress((void**)&p_x2,       g_x2);
    cudaGetSymbolAddress((void**)&p_h2,       g_h2);
    cudaGetSymbolAddress((void**)&p_is64,     g_is64);

    const int T = 256;
    int nblk = (n + SCAN_B - 1) / SCAN_B;

    detect_dtype<<<1, 32>>>((const int*)ei, p_is64);
    cudaMemsetAsync(p_hist, 0, (size_t)n * sizeof(int));
    prep_edges<<<(nE + T - 1) / T, T>>>(ei, p_src, p_dst, p_hist, p_is64, nE, n);
    block_scan<<<nblk, SCAN_B>>>(p_hist, p_rowptr, p_bsum, p_dinv, n);
    scan_sums<<<1, SCAN_B>>>(p_bsum, p_boff, p_rowptr, n, nblk);
    add_offsets<<<nblk, SCAN_B>>>(p_rowptr, p_fill, p_boff, n);
    fill_csr<<<(nE + T - 1) / T, T>>>(p_src, p_dst, p_dinv, p_fill, p_csr_src, p_csr_norm, nE);

    // layer 1: gemm + fused aggregate/self/bias/relu
    gemm128<<<(n + 63) / 64, T>>>(x, W1, p_h1, n);
    aggregate128<<<(n + 7) / 8, T>>>(p_h1, p_rowptr, p_csr_src, p_csr_norm, p_dinv, b1, p_x2, n);

    // layer 2
    gemm64<<<(n + 63) / 64, T>>>(p_x2, W2, p_h2, n);
    aggregate64<<<(n + 7) / 8, T>>>(p_h2, p_rowptr, p_csr_src, p_csr_norm, p_dinv, b2, out, n);
}